// round 7
// baseline (speedup 1.0000x reference)
#include <cuda_runtime.h>
#include <cuda_bf16.h>
#include <cstdint>

#define NPL    16384
#define DEG    16
#define DIM    128
#define NT     512
#define GRIDSZ 148
#define NTILES 256    // 64-row tiles per level

// weight blob offsets (per MLP, bytes). [N][K] bf16, XOR-16B swizzle
#define WL1H 0
#define WL1L 16384      // 64 x 256B
#define WL2H 32768
#define WL2L 40960      // 64 x 128B
#define WL3H 49152
#define WL3L 65536      // 128 x 128B
#define WBLOB 81920

// smem layout (bytes)
#define OFF_W    0              // ONE MLP blob resident per phase: 81920
#define OFF_A0H  81920          // A buf0 hi [64][256B]
#define OFF_A0L  98304
#define OFF_A1H  114688         // A buf1
#define OFF_A1L  131072
#define OFF_BH   147456         // L1 out [64][128B]
#define OFF_BL   155648
#define OFF_CH   163840         // L2 out [64][128B]
#define OFF_CL   172032
#define OFF_IDX0 180224         // src 4096 + mask 4096 per buf
#define OFF_IDX1 188416
#define OFF_BIAS 196608         // 512 floats
#define SM_TOTAL 198656

// named barrier ids
#define BAR_FULL0  1
#define BAR_FULL1  2
#define BAR_EMPTY0 3
#define BAR_EMPTY1 4
#define BAR_PROD   5
#define BAR_CONS   6

#define NBAR_SYNC(id, cnt)   asm volatile("bar.sync %0, %1;"   :: "r"(id), "r"(cnt) : "memory")
#define NBAR_ARRIVE(id, cnt) asm volatile("bar.arrive %0, %1;" :: "r"(id), "r"(cnt) : "memory")

__device__ __align__(16) float   g_inv[7 * NPL * DIM];
__device__ __align__(16) uint8_t g_wb[2 * WBLOB];
__device__ unsigned g_bar;

__device__ __forceinline__ float leaky(float v) { return v >= 0.f ? v : 0.01f * v; }

__device__ __forceinline__ void split2(float f0, float f1, uint32_t& hi, uint32_t& lo) {
    asm("cvt.rn.bf16x2.f32 %0, %1, %2;" : "=r"(hi) : "f"(f1), "f"(f0));
    float hf0 = __uint_as_float(hi << 16);
    float hf1 = __uint_as_float(hi & 0xFFFF0000u);
    float r0 = f0 - hf0, r1 = f1 - hf1;
    asm("cvt.rn.bf16x2.f32 %0, %1, %2;" : "=r"(lo) : "f"(r1), "f"(r0));
}

__device__ __forceinline__ uint32_t smem_u32(const void* p) {
    uint32_t a;
    asm("{ .reg .u64 t; cvta.to.shared.u64 t, %1; cvt.u32.u64 %0, t; }" : "=r"(a) : "l"(p));
    return a;
}
__device__ __forceinline__ void ldm4(uint32_t addr, uint32_t r[4]) {
    asm volatile("ldmatrix.sync.aligned.m8n8.x4.shared.b16 {%0,%1,%2,%3}, [%4];"
                 : "=r"(r[0]), "=r"(r[1]), "=r"(r[2]), "=r"(r[3]) : "r"(addr));
}
__device__ __forceinline__ void mma16816(float c[4], const uint32_t a[4],
                                         uint32_t b0, uint32_t b1) {
    asm volatile("mma.sync.aligned.m16n8k16.row.col.f32.bf16.bf16.f32 "
                 "{%0,%1,%2,%3}, {%4,%5,%6,%7}, {%8,%9}, {%0,%1,%2,%3};"
                 : "+f"(c[0]), "+f"(c[1]), "+f"(c[2]), "+f"(c[3])
                 : "r"(a[0]), "r"(a[1]), "r"(a[2]), "r"(a[3]), "r"(b0), "r"(b1));
}

// ---------------- grid barrier (all GRIDSZ CTAs resident) ----------------
__device__ __forceinline__ void grid_barrier(unsigned target) {
    __syncthreads();
    if (threadIdx.x == 0) {
        asm volatile("red.release.gpu.add.u32 [%0], 1;" :: "l"(&g_bar) : "memory");
        unsigned v;
        do {
            asm volatile("ld.acquire.gpu.u32 %0, [%1];" : "=r"(v) : "l"(&g_bar) : "memory");
        } while (v < target);
    }
    __syncthreads();
}

// ---------------- weight prep: fp32 [K][N] -> bf16 hi/lo [N][K] swizzled ----------------
__global__ void prep_weights(const float* aw1, const float* aw2, const float* aw3,
                             const float* iw1, const float* iw2, const float* iw3)
{
    if (blockIdx.x == 0 && threadIdx.x == 0) g_bar = 0;
    const int b = blockIdx.x;
    const int layer = b % 3;
    const uint32_t base = (b < 3) ? 0u : (uint32_t)WBLOB;
    const float* W; int K, N; uint32_t offH, offL;
    if (layer == 0)      { K = 128; N = 64;  offH = WL1H; offL = WL1L; W = (b < 3) ? aw1 : iw1; }
    else if (layer == 1) { K = 64;  N = 64;  offH = WL2H; offL = WL2L; W = (b < 3) ? aw2 : iw2; }
    else                 { K = 64;  N = 128; offH = WL3H; offL = WL3L; W = (b < 3) ? aw3 : iw3; }
    uint8_t* oH = g_wb + base + offH;
    uint8_t* oL = g_wb + base + offL;
    const uint32_t stride = (uint32_t)K * 2u;
    for (int idx = threadIdx.x; idx < N * K; idx += blockDim.x) {
        const int n = idx / K, k = idx % K;
        float f = W[k * N + n];
        __nv_bfloat16 hv = __float2bfloat16(f);
        __nv_bfloat16 lv = __float2bfloat16(f - __bfloat162float(hv));
        const uint32_t byte = (uint32_t)n * stride +
                              ((((uint32_t)(k >> 3) ^ (uint32_t)(n & 7)) << 4)) +
                              (uint32_t)(k & 7) * 2u;
        *(__nv_bfloat16*)(oH + byte) = hv;
        *(__nv_bfloat16*)(oL + byte) = lv;
    }
}

// ---------------- warp-tile GEMM: both A and W sides XOR-swizzled ----------------
template <int KSTEPS, int NB8>
__device__ __forceinline__ void mma_swz(uint32_t aHi, uint32_t aLo, uint32_t strideA,
                                        uint32_t wHi, uint32_t wLo, uint32_t strideW,
                                        int mt, int n0, int lane, float acc[][4])
{
#pragma unroll
    for (int i = 0; i < NB8; i++) { acc[i][0] = acc[i][1] = acc[i][2] = acc[i][3] = 0.f; }
    const int arow = mt * 16 + (lane & 15);
    const uint32_t abase = (uint32_t)arow * strideA;
    const uint32_t asel = (uint32_t)(lane >> 4);
    const int brow = lane & 15;
    const uint32_t bsel = (uint32_t)(lane >> 4);
#pragma unroll
    for (int kb = 0; kb < KSTEPS; kb++) {
        const uint32_t au = ((((uint32_t)kb * 2u + asel) ^ (uint32_t)(arow & 7)) << 4);
        uint32_t ah[4], al[4];
        ldm4(aHi + abase + au, ah);
        ldm4(aLo + abase + au, al);
#pragma unroll
        for (int s = 0; s < NB8 / 2; s++) {
            const int n = n0 + s * 16 + brow;
            const uint32_t c = ((uint32_t)kb << 1) | bsel;
            const uint32_t boff = (uint32_t)n * strideW + ((c ^ (uint32_t)(n & 7)) << 4);
            uint32_t bh[4], bl[4];
            ldm4(wHi + boff, bh);
            ldm4(wLo + boff, bl);
            mma16816(acc[s * 2 + 0], ah, bh[0], bh[2]);
            mma16816(acc[s * 2 + 0], ah, bl[0], bl[2]);
            mma16816(acc[s * 2 + 0], al, bh[0], bh[2]);
            mma16816(acc[s * 2 + 1], ah, bh[1], bh[3]);
            mma16816(acc[s * 2 + 1], ah, bl[1], bl[3]);
            mma16816(acc[s * 2 + 1], al, bh[1], bh[3]);
        }
    }
}

// ---------------- mid epilogue: bias+leaky+split -> swizzled smem ----------------
template <int NB8>
__device__ __forceinline__ void epi_mid(const float acc[][4], const float* bias,
                                        uint8_t* smem, uint32_t outHi, uint32_t outLo,
                                        uint32_t strideOut, int mt, int n0, int lane)
{
    const int qr = lane >> 2, qc = (lane & 3) * 2;
#pragma unroll
    for (int nf = 0; nf < NB8; nf++) {
        const int col = n0 + nf * 8 + qc;
        const float b0 = bias[col], b1 = bias[col + 1];
#pragma unroll
        for (int hf = 0; hf < 2; hf++) {
            const int row = mt * 16 + qr + hf * 8;
            float f0 = leaky(acc[nf][hf * 2 + 0] + b0);
            float f1 = leaky(acc[nf][hf * 2 + 1] + b1);
            uint32_t hi, lo; split2(f0, f1, hi, lo);
            const uint32_t byte = (uint32_t)row * strideOut +
                ((((uint32_t)(col >> 3)) ^ (uint32_t)(row & 7)) << 4) + (uint32_t)(col & 7) * 2u;
            *(uint32_t*)(smem + outHi + byte) = hi;
            *(uint32_t*)(smem + outLo + byte) = lo;
        }
    }
}

// ---------------- final epilogue: bias -> gmem fp32 ----------------
__device__ __forceinline__ void epi_final(const float acc[][4], const float* bias,
                                          float* __restrict__ gout, int mt, int n0, int lane)
{
    const int qr = lane >> 2, qc = (lane & 3) * 2;
#pragma unroll
    for (int nf = 0; nf < 8; nf++) {
        const int col = n0 + nf * 8 + qc;
        const float b0 = bias[col], b1 = bias[col + 1];
#pragma unroll
        for (int hf = 0; hf < 2; hf++) {
            const int row = mt * 16 + qr + hf * 8;
            *(float2*)&gout[(size_t)row * DIM + col] =
                make_float2(acc[nf][hf * 2 + 0] + b0, acc[nf][hf * 2 + 1] + b1);
        }
    }
}

// ---------------- producer fills ----------------
__device__ __forceinline__ void store_row_swz(uint8_t* smem, uint32_t aH, uint32_t aL,
                                              int row, int lane, float4 v)
{
    uint32_t h0, l0, h1, l1;
    split2(v.x, v.y, h0, l0);
    split2(v.z, v.w, h1, l1);
    const uint32_t byte = (uint32_t)row * 256u +
        ((((uint32_t)(lane >> 1)) ^ (uint32_t)(row & 7)) << 4) + (uint32_t)(lane & 1) * 8u;
    *(uint2*)(smem + aH + byte) = make_uint2(h0, h1);
    *(uint2*)(smem + aL + byte) = make_uint2(l0, l1);
}

__device__ __forceinline__ void fill_contig(uint8_t* smem, uint32_t aH, uint32_t aL,
                                            const float* __restrict__ in, int nodebase, int ptid)
{
    const float4* in4 = (const float4*)(in + (size_t)nodebase * DIM);
    for (int i = ptid; i < 64 * 32; i += 256) {
        const int row = i >> 5, c4 = i & 31;
        float4 x = in4[(size_t)row * 32 + c4];
        uint32_t h0, l0, h1, l1;
        split2(x.x, x.y, h0, l0);
        split2(x.z, x.w, h1, l1);
        const uint32_t byte = (uint32_t)row * 256u +
            ((((uint32_t)(c4 >> 1)) ^ (uint32_t)(row & 7)) << 4) + (uint32_t)(c4 & 1) * 8u;
        *(uint2*)(smem + aH + byte) = make_uint2(h0, h1);
        *(uint2*)(smem + aL + byte) = make_uint2(l0, l1);
    }
}

__device__ __forceinline__ void fill_gather(uint8_t* smem, uint32_t aH, uint32_t aL,
                                            uint32_t idxoff,
                                            const float* __restrict__ h,
                                            const float* __restrict__ ginv,
                                            const int* __restrict__ src,
                                            const int* __restrict__ msk,
                                            int nodebase, int pw, int lane, int ptid)
{
    ((int4*)(smem + idxoff))[ptid]        = ((const int4*)(src + (size_t)nodebase * DEG))[ptid];
    ((int4*)(smem + idxoff + 4096))[ptid] = ((const int4*)(msk + (size_t)nodebase * DEG))[ptid];
    NBAR_SYNC(BAR_PROD, 256);
    const int* sidx = (const int*)(smem + idxoff);
    const int* midx = sidx + 1024;
#pragma unroll
    for (int rr = 0; rr < 8; rr += 2) {
        const int r0 = pw * 8 + rr, r1 = r0 + 1;
        float4 a0 = make_float4(0.f, 0.f, 0.f, 0.f);
        float4 a1 = make_float4(0.f, 0.f, 0.f, 0.f);
#pragma unroll 8
        for (int e = 0; e < DEG; e++) {
            const int s0 = sidx[r0 * DEG + e], m0 = midx[r0 * DEG + e];
            const int s1 = sidx[r1 * DEG + e], m1 = midx[r1 * DEG + e];
            const float4* p0 = (const float4*)((m0 ? ginv : h) + (size_t)s0 * DIM);
            const float4* p1 = (const float4*)((m1 ? ginv : h) + (size_t)s1 * DIM);
            float4 v0 = p0[lane], v1 = p1[lane];
            a0.x += v0.x; a0.y += v0.y; a0.z += v0.z; a0.w += v0.w;
            a1.x += v1.x; a1.y += v1.y; a1.z += v1.z; a1.w += v1.w;
        }
        const float s16 = 0.0625f;
        a0.x *= s16; a0.y *= s16; a0.z *= s16; a0.w *= s16;
        a1.x *= s16; a1.y *= s16; a1.z *= s16; a1.w *= s16;
        store_row_swz(smem, aH, aL, r0, lane, a0);
        store_row_swz(smem, aH, aL, r1, lane, a1);
    }
}

// ---------------- consumer: one tile through the 3-layer MLP ----------------
__device__ __forceinline__ void consumer_tile(uint8_t* smem, uint32_t SB, int buf,
                                              const float* bias, float* __restrict__ gout,
                                              int mt, int nh, int lane)
{
    float acc[8][4];
    const uint32_t aH = SB + (buf ? OFF_A1H : OFF_A0H);
    const uint32_t aL = SB + (buf ? OFF_A1L : OFF_A0L);
    NBAR_SYNC(BAR_FULL0 + buf, 512);
    mma_swz<8, 4>(aH, aL, 256, SB + OFF_W + WL1H, SB + OFF_W + WL1L, 256, mt, nh * 32, lane, acc);
    NBAR_ARRIVE(BAR_EMPTY0 + buf, 512);
    epi_mid<4>(acc, bias, smem, OFF_BH, OFF_BL, 128, mt, nh * 32, lane);
    NBAR_SYNC(BAR_CONS, 256);
    mma_swz<4, 4>(SB + OFF_BH, SB + OFF_BL, 128, SB + OFF_W + WL2H, SB + OFF_W + WL2L, 128,
                  mt, nh * 32, lane, acc);
    epi_mid<4>(acc, bias + 64, smem, OFF_CH, OFF_CL, 128, mt, nh * 32, lane);
    NBAR_SYNC(BAR_CONS, 256);
    mma_swz<4, 8>(SB + OFF_CH, SB + OFF_CL, 128, SB + OFF_W + WL3H, SB + OFF_W + WL3L, 128,
                  mt, nh * 64, lane, acc);
    epi_final(acc, bias + 128, gout, mt, nh * 64, lane);
}

// ---------------- one phase: pipelined producer/consumer over tiles ----------------
__device__ void run_phase(uint8_t* smem, uint32_t SB, int gather,
                          const float* __restrict__ in,
                          const int* __restrict__ src, const int* __restrict__ msk,
                          const float* __restrict__ hfull,
                          float* __restrict__ out,
                          uint32_t wsrc, const float* bias,
                          int lane, int w, int tid)
{
    if (w < 8) {
        // ---- producer ----
        int i = 0;
        for (int t = blockIdx.x; t < NTILES; t += GRIDSZ, i++) {
            const int buf = i & 1;
            if (i >= 2) NBAR_SYNC(BAR_EMPTY0 + buf, 512);
            const int nodebase = t * 64;
            const uint32_t aH = buf ? OFF_A1H : OFF_A0H;
            const uint32_t aL = buf ? OFF_A1L : OFF_A0L;
            if (gather)
                fill_gather(smem, aH, aL, buf ? OFF_IDX1 : OFF_IDX0,
                            hfull, g_inv, src, msk, nodebase, w, lane, tid);
            else
                fill_contig(smem, aH, aL, in, nodebase, tid);
            __threadfence_block();
            NBAR_ARRIVE(BAR_FULL0 + buf, 512);
        }
        // drain consumer EMPTY arrivals for the last min(i,2) tiles
        const int start = (i >= 2) ? i - 2 : 0;
        for (int j = start; j < i; j++) NBAR_SYNC(BAR_EMPTY0 + (j & 1), 512);
    } else {
        // ---- consumer: stage this phase's weights, then process tiles ----
        {
            const uint4* s4 = (const uint4*)(g_wb + wsrc);
            uint4* d4 = (uint4*)(smem + OFF_W);
            for (int k = tid - 256; k < WBLOB / 16; k += 256) d4[k] = s4[k];
        }
        const int cw = w - 8, mt = cw & 3, nh = cw >> 2;
        int i = 0;
        for (int t = blockIdx.x; t < NTILES; t += GRIDSZ, i++) {
            consumer_tile(smem, SB, i & 1, bias, out + (size_t)t * 64 * DIM, mt, nh, lane);
        }
    }
}

// ---------------- persistent kernel ----------------
__global__ __launch_bounds__(NT, 1)
void persist_kernel(const float* __restrict__ hin, float* __restrict__ h,
                    const int* __restrict__ esrc, const int* __restrict__ emask,
                    const float* ab1, const float* ab2, const float* ab3,
                    const float* ib1, const float* ib2, const float* ib3)
{
    extern __shared__ __align__(16) uint8_t smem[];
    const uint32_t SB = smem_u32(smem);
    const int tid = threadIdx.x, lane = tid & 31, w = tid >> 5;
    float* BIAS = (float*)(smem + OFF_BIAS);

    if (tid < 64) {
        BIAS[tid] = ab1[tid];       BIAS[64 + tid] = ab2[tid];
        BIAS[256 + tid] = ib1[tid]; BIAS[320 + tid] = ib2[tid];
    }
    if (tid < 128) { BIAS[128 + tid] = ab3[tid]; BIAS[384 + tid] = ib3[tid]; }
    __syncthreads();

    unsigned bt = 0;

    // phase 0: inv-MLP over level-0 input rows (contiguous)
    run_phase(smem, SB, 0, hin, nullptr, nullptr, nullptr,
              g_inv, WBLOB, BIAS + 256, lane, w, tid);
    bt += GRIDSZ; grid_barrier(bt);

    for (int lvl = 0; lvl < 7; lvl++) {
        const int* src = esrc  + (size_t)lvl * NPL * DEG;
        const int* msk = emask + (size_t)lvl * NPL * DEG;
        float* hlvl = h + (size_t)(lvl + 1) * NPL * DIM;

        // AND phase: gather -> and-MLP -> h[lvl+1]
        run_phase(smem, SB, 1, nullptr, src, msk, h, hlvl, 0, BIAS, lane, w, tid);

        if (lvl < 6) {
            bt += GRIDSZ; grid_barrier(bt);
            // INV phase: h[lvl+1] (contiguous) -> inv-MLP -> g_inv[lvl+1]
            float* gilvl = g_inv + (size_t)(lvl + 1) * NPL * DIM;
            run_phase(smem, SB, 0, hlvl, nullptr, nullptr, nullptr,
                      gilvl, WBLOB, BIAS + 256, lane, w, tid);
            bt += GRIDSZ; grid_barrier(bt);
        }
    }
}

// ---------------------------------------------------------------------------
extern "C" void kernel_launch(void* const* d_in, const int* in_sizes, int n_in,
                              void* d_out, int out_size)
{
    (void)in_sizes; (void)n_in; (void)out_size;
    const float* h_in  = (const float*)d_in[0];
    const int*   esrc  = (const int*)d_in[1];
    const int*   emask = (const int*)d_in[2];
    const float* iw1 = (const float*)d_in[3];
    const float* ib1 = (const float*)d_in[4];
    const float* iw2 = (const float*)d_in[5];
    const float* ib2 = (const float*)d_in[6];
    const float* iw3 = (const float*)d_in[7];
    const float* ib3 = (const float*)d_in[8];
    const float* aw1 = (const float*)d_in[9];
    const float* ab1 = (const float*)d_in[10];
    const float* aw2 = (const float*)d_in[11];
    const float* ab2 = (const float*)d_in[12];
    const float* aw3 = (const float*)d_in[13];
    const float* ab3 = (const float*)d_in[14];

    float* h = (float*)d_out;

    static bool once = false;
    if (!once) {
        cudaFuncSetAttribute(persist_kernel, cudaFuncAttributeMaxDynamicSharedMemorySize, SM_TOTAL);
        once = true;
    }

    // level-0 rows of the output are the input rows
    cudaMemcpyAsync(h, h_in, (size_t)NPL * DIM * sizeof(float), cudaMemcpyDeviceToDevice, 0);

    // converts weights AND resets g_bar (deterministic per launch / graph replay)
    prep_weights<<<6, 256>>>(aw1, aw2, aw3, iw1, iw2, iw3);

    persist_kernel<<<GRIDSZ, NT, SM_TOTAL>>>(h_in, h, esrc, emask,
                                             ab1, ab2, ab3, ib1, ib2, ib3);
}